// round 1
// baseline (speedup 1.0000x reference)
#include <cuda_runtime.h>
#include <math.h>

// Problem constants (fixed by the reference: x = (4, 64, 128, 128) fp32, K=7)
#define BATCH   4
#define CHN     64
#define HT      128
#define WD      128
#define KW      7
#define PADR    3
#define TILE    16
#define TR      (TILE + 2 * PADR)   // 22 rows/cols incl. halo
#define NPIX    (TR * TR)           // 484 tile pixels
#define CPAD    68                  // channel stride pad (bank-shift 4 -> free for LDS.128)
#define NTHREADS 256
#define NOFF    (KW * KW)           // 49
#define EPSV    1e-7f

// smem layout: tile [NPIX][CPAD] | norms [NPIX] | sims [NOFF][NTHREADS]
#define SMEM_TILE_F   (NPIX * CPAD)                       // 32912 floats
#define SMEM_NORM_F   (NPIX)                              // 484
#define SMEM_SIMS_F   (NOFF * NTHREADS)                   // 12544
#define SMEM_BYTES    ((SMEM_TILE_F + SMEM_NORM_F + SMEM_SIMS_F) * 4)  // 183,760 B

__global__ __launch_bounds__(NTHREADS, 1)
void region_sim_kernel(const float* __restrict__ x, float* __restrict__ out) {
    extern __shared__ float smem[];
    float* tile  = smem;                       // [NPIX][CPAD], channel-last
    float* norms = tile + SMEM_TILE_F;         // [NPIX]
    float* sims  = norms + SMEM_NORM_F;        // [NOFF][NTHREADS]

    const int b   = blockIdx.z;
    const int w0  = blockIdx.x * TILE;
    const int h0  = blockIdx.y * TILE;
    const int tid = threadIdx.x;

    // ---- Phase 1: load halo'd tile (gmem coalesced along w; smem write bank-shift 4) ----
    const float* xb = x + (size_t)b * CHN * HT * WD;
    for (int i = tid; i < NPIX * CHN; i += NTHREADS) {
        int c   = i / NPIX;
        int rem = i - c * NPIX;
        int r   = rem / TR;
        int cc  = rem - r * TR;
        int gh  = h0 - PADR + r;
        int gw  = w0 - PADR + cc;
        float v = 0.0f;
        if (gh >= 0 && gh < HT && gw >= 0 && gw < WD)
            v = xb[(c * HT + gh) * WD + gw];
        tile[rem * CPAD + c] = v;
    }
    __syncthreads();

    // ---- Phase 2: per-pixel L2 norm over channels (reused for center AND patches) ----
    for (int p = tid; p < NPIX; p += NTHREADS) {
        const float4* tp = (const float4*)(tile + p * CPAD);
        float4 s = make_float4(0.f, 0.f, 0.f, 0.f);
        #pragma unroll
        for (int q = 0; q < CHN / 4; q++) {
            float4 v = tp[q];
            s.x += v.x * v.x; s.y += v.y * v.y;
            s.z += v.z * v.z; s.w += v.w * v.w;
        }
        norms[p] = sqrtf(s.x + s.y + s.z + s.w);
    }
    __syncthreads();

    // ---- Phase 3: register the center vector, stream neighbors from smem ----
    const int lw   = tid & (TILE - 1);
    const int lh   = tid >> 4;
    const int cpix = (lh + PADR) * TR + (lw + PADR);

    float4 cen[CHN / 4];
    {
        const float4* cp = (const float4*)(tile + cpix * CPAD);
        #pragma unroll
        for (int q = 0; q < CHN / 4; q++) cen[q] = cp[q];
    }
    const float nc = norms[cpix];

    float denom = 0.0f;
    #pragma unroll 1
    for (int di = -PADR; di <= PADR; di++) {
        #pragma unroll 1
        for (int dj = -PADR; dj <= PADR; dj++) {
            const int npx = cpix + di * TR + dj;
            const float4* np4 = (const float4*)(tile + npx * CPAD);
            float4 a = make_float4(0.f, 0.f, 0.f, 0.f);
            #pragma unroll
            for (int q = 0; q < CHN / 4; q++) {
                float4 v = np4[q];
                a.x += cen[q].x * v.x; a.y += cen[q].y * v.y;
                a.z += cen[q].z * v.z; a.w += cen[q].w * v.w;
            }
            float dot = (a.x + a.y) + (a.z + a.w);
            float sim = dot / (nc * norms[npx] + EPSV);
            float e = __expf(sim);                 // sim in [-1,1]: no max-sub needed
            int kk = (di + PADR) * KW + (dj + PADR);
            sims[kk * NTHREADS + tid] = e;         // [kk][tid]: conflict-free both ways
            denom += e;
        }
    }
    // each thread only reads back its own sims -> no barrier needed

    // ---- Phase 4: normalize + coalesced store, out[b][kk][h*W + w] ----
    const float rinv = 1.0f / denom;
    const size_t obase = (size_t)b * NOFF * (HT * WD) + (size_t)(h0 + lh) * WD + (w0 + lw);
    #pragma unroll 1
    for (int kk = 0; kk < NOFF; kk++) {
        out[obase + (size_t)kk * (HT * WD)] = sims[kk * NTHREADS + tid] * rinv;
    }
}

extern "C" void kernel_launch(void* const* d_in, const int* in_sizes, int n_in,
                              void* d_out, int out_size) {
    (void)in_sizes; (void)n_in; (void)out_size;
    const float* x = (const float*)d_in[0];
    float* out = (float*)d_out;

    cudaFuncSetAttribute(region_sim_kernel,
                         cudaFuncAttributeMaxDynamicSharedMemorySize, SMEM_BYTES);

    dim3 grid(WD / TILE, HT / TILE, BATCH);   // 8 x 8 x 4 = 256 blocks
    region_sim_kernel<<<grid, NTHREADS, SMEM_BYTES>>>(x, out);
}

// round 3
// speedup vs baseline: 1.2273x; 1.2273x over previous
#include <cuda_runtime.h>
#include <math.h>

// x = (4, 64, 128, 128) fp32, K=7 -> out (4, 49, 16384) fp32
#define BATCH   4
#define CHN     64
#define HT      128
#define WD      128
#define HW      (HT * WD)            // 16384
#define KW      7
#define PADR    3
#define TILEH   32                   // rows per block (2 per thread)
#define TILEW   16                   // cols per block
#define TRH     (TILEH + 2 * PADR)   // 38
#define TRW     (TILEW + 2 * PADR)   // 22
#define NPIX    (TRH * TRW)          // 836
#define NTHREADS 256
#define NOFF    (KW * KW)            // 49
#define EPSV    1e-7f

// smem: swizzled tile [NPIX][64] + norms [NPIX]
#define SMEM_TILE_F  (NPIX * 64)                    // 53504 floats
#define SMEM_BYTES   ((SMEM_TILE_F + NPIX) * 4)     // 217,360 B (< 227KB limit)

// One neighbor pixel: 16 swizzled LDS.128, feeds dot(s) for center A and/or B,
// then exp -> gmem (unnormalized) + running denominator.
template<bool UA, bool UB>
__device__ __forceinline__ void neigh(const float* __restrict__ tile,
                                      const float* __restrict__ norms,
                                      int pn,
                                      const float4* cA, const float4* cB,
                                      float nA, float nB,
                                      float& denA, float& denB,
                                      float* __restrict__ out,
                                      size_t oA, size_t oB)
{
    const float* nb = tile + pn * 64;
    const int sw = pn & 15;
    float4 aA = make_float4(0.f, 0.f, 0.f, 0.f);
    float4 aB = make_float4(0.f, 0.f, 0.f, 0.f);
#pragma unroll
    for (int q = 0; q < 16; q++) {
        float4 v = *(const float4*)(nb + ((q ^ sw) << 2));
        if (UA) {
            aA.x += cA[q].x * v.x; aA.y += cA[q].y * v.y;
            aA.z += cA[q].z * v.z; aA.w += cA[q].w * v.w;
        }
        if (UB) {
            aB.x += cB[q].x * v.x; aB.y += cB[q].y * v.y;
            aB.z += cB[q].z * v.z; aB.w += cB[q].w * v.w;
        }
    }
    const float nn = norms[pn];
    if (UA) {
        float dot = (aA.x + aA.y) + (aA.z + aA.w);
        float e = __expf(__fdividef(dot, nA * nn + EPSV));  // sim in [-1,1]
        denA += e;
        out[oA] = e;
    }
    if (UB) {
        float dot = (aB.x + aB.y) + (aB.z + aB.w);
        float e = __expf(__fdividef(dot, nB * nn + EPSV));
        denB += e;
        out[oB] = e;
    }
}

__global__ __launch_bounds__(NTHREADS, 1)
void region_sim_kernel(const float* __restrict__ x, float* __restrict__ out) {
    extern __shared__ float smem[];
    float* tile  = smem;                 // [NPIX][64], chunk-swizzled channel-last
    float* norms = tile + SMEM_TILE_F;   // [NPIX]

    const int b   = blockIdx.z;
    const int w0  = blockIdx.x * TILEW;
    const int h0  = blockIdx.y * TILEH;
    const int tid = threadIdx.x;

    // ---- Phase 1: load halo'd tile, float4 per (pixel, chunk), XOR-swizzled ----
    // Outer loop over pixels (bounds/indices computed once), inner over channel chunks.
    const float* xb = x + (size_t)b * CHN * HW;
#pragma unroll 1
    for (int p = tid; p < NPIX; p += NTHREADS) {
        int r   = p / TRW;
        int col = p - r * TRW;
        int gh  = h0 - PADR + r;
        int gw  = w0 - PADR + col;
        const bool inb = (gh >= 0 && gh < HT && gw >= 0 && gw < WD);
        const int gi = gh * WD + gw;
        float* tp = tile + p * 64;
        const int sw = p & 15;
#pragma unroll 1
        for (int q = 0; q < 16; q++) {
            float4 v = make_float4(0.f, 0.f, 0.f, 0.f);
            if (inb) {
                const float* x0 = xb + (size_t)(q * 4) * HW + gi;
                v.x = x0[0];
                v.y = x0[HW];
                v.z = x0[2 * HW];
                v.w = x0[3 * HW];
            }
            *(float4*)(tp + ((q ^ sw) << 2)) = v;
        }
    }
    __syncthreads();

    // ---- Phase 2: per-pixel L2 norms (order-invariant sum, swizzled reads) ----
#pragma unroll 1
    for (int p = tid; p < NPIX; p += NTHREADS) {
        const float* tp = tile + p * 64;
        const int sw = p & 15;
        float4 s = make_float4(0.f, 0.f, 0.f, 0.f);
#pragma unroll
        for (int q = 0; q < 16; q++) {
            float4 v = *(const float4*)(tp + ((q ^ sw) << 2));
            s.x += v.x * v.x; s.y += v.y * v.y;
            s.z += v.z * v.z; s.w += v.w * v.w;
        }
        norms[p] = sqrtf((s.x + s.y) + (s.z + s.w));
    }
    __syncthreads();

    // ---- Phase 3: two vertically-adjacent centers per thread ----
    const int lw   = tid & (TILEW - 1);     // 0..15
    const int lhp  = tid >> 4;              // 0..15 (row-pair)
    const int rA   = PADR + 2 * lhp;        // tile row of center A
    const int colC = PADR + lw;
    const int pA   = rA * TRW + colC;
    const int pB   = pA + TRW;

    float4 cA[16], cB[16];
    {
        const float* ta = tile + pA * 64;
        const float* tb = tile + pB * 64;
        const int swA = pA & 15, swB = pB & 15;
#pragma unroll
        for (int q = 0; q < 16; q++) {
            cA[q] = *(const float4*)(ta + ((q ^ swA) << 2));
            cB[q] = *(const float4*)(tb + ((q ^ swB) << 2));
        }
    }
    const float nA = norms[pA];
    const float nB = norms[pB];

    float denA = 0.f, denB = 0.f;
    const size_t obaseA = (size_t)b * NOFF * HW + (size_t)(h0 + 2 * lhp) * WD + (w0 + lw);
    const size_t obaseB = obaseA + WD;

    // o = -3: only center A's top row
#pragma unroll 1
    for (int dj = -PADR; dj <= PADR; dj++) {
        int pn = (rA - 3) * TRW + colC + dj;
        neigh<true, false>(tile, norms, pn, cA, cB, nA, nB, denA, denB,
                           out, obaseA + (size_t)(dj + 3) * HW, 0);
    }
    // o = -2..3: shared rows — one neighbor load feeds both centers
#pragma unroll 1
    for (int o = -2; o <= 3; o++) {
#pragma unroll 1
        for (int dj = -PADR; dj <= PADR; dj++) {
            int pn = (rA + o) * TRW + colC + dj;
            int kkA = (o + 3) * KW + (dj + 3);
            int kkB = (o + 2) * KW + (dj + 3);
            neigh<true, true>(tile, norms, pn, cA, cB, nA, nB, denA, denB,
                              out, obaseA + (size_t)kkA * HW, obaseB + (size_t)kkB * HW);
        }
    }
    // o = +4: only center B's bottom row
#pragma unroll 1
    for (int dj = -PADR; dj <= PADR; dj++) {
        int pn = (rA + 4) * TRW + colC + dj;
        neigh<false, true>(tile, norms, pn, cA, cB, nA, nB, denA, denB,
                           out, 0, obaseB + (size_t)(42 + dj + 3) * HW);
    }

    // ---- Phase 4: normalize in-place (L2-resident; same-thread RAW, no barrier) ----
    const float riA = __fdividef(1.f, denA);
    const float riB = __fdividef(1.f, denB);
#pragma unroll 1
    for (int kk = 0; kk < NOFF; kk++) {
        float ea = out[obaseA + (size_t)kk * HW];
        float eb = out[obaseB + (size_t)kk * HW];
        out[obaseA + (size_t)kk * HW] = ea * riA;
        out[obaseB + (size_t)kk * HW] = eb * riB;
    }
}

extern "C" void kernel_launch(void* const* d_in, const int* in_sizes, int n_in,
                              void* d_out, int out_size) {
    (void)in_sizes; (void)n_in; (void)out_size;
    const float* x = (const float*)d_in[0];
    float* out = (float*)d_out;

    cudaFuncSetAttribute(region_sim_kernel,
                         cudaFuncAttributeMaxDynamicSharedMemorySize, SMEM_BYTES);

    dim3 grid(WD / TILEW, HT / TILEH, BATCH);   // 8 x 4 x 4 = 128 blocks = 1 wave
    region_sim_kernel<<<grid, NTHREADS, SMEM_BYTES>>>(x, out);
}